// round 11
// baseline (speedup 1.0000x reference)
#include <cuda_runtime.h>

// Biquad DF2T, B=512 channels, T=48000, fp32.
// s[n] = M s[n-1] + g x[n],  M = [[-a1,1],[-a2,0]] per-channel constant.
//
// 4 segments/channel (2048 blocks). 375 chunks x 32 samples per segment,
// one chunk per thread. Q = M^32, P = Q^375 = M^SEG.
//   passA : zero-state recurrence per chunk -> y0 in smem + end state d_i
//   scan  : shuffle two-level affine scan; segment state injected at the
//           cross-warp level via  E^_w = E_w + (Q^32)^(w+1) s_in
//   store : y = y0 + row0(M^j) . sv_in[chunk], fused into float4 STG
// De-chained look-back: every segment publishes its ZERO-STATE total D_seg
// (independent of all other segments); seg k's thread 511 (idle in passA)
// spins for D_{<k} and combines s_in = sum P^j D_{k-1-j}. Chain depth 1.
// ~54KB smem, 32 regs -> 4 CTAs/SM.

#define NCHAN   512
#define TLEN    48000
#define NSEG    4
#define SEG     12000
#define CHUNK   32
#define NCH     375
#define STRIDE  33          // CHUNK+1, odd -> conflict-free rows
#define THREADS 512
#define NBLK    (NCHAN * NSEG)
#define NF4     (SEG / 4)   // 3000

struct SmemLayout {
    float4 gt[32];             // Q^(lane+1)
    float4 gt2[16];            // (Q^32)^(w+1)
    float2 mj[CHUNK];          // row0 of M^j, j=0..31
    float2 sv_in[384];         // incoming true state per chunk
    float2 warp_agg[16];
    float2 warp_E[16];         // zero-state cross-warp prefix
    float2 warp_E2[16];        // seeded cross-warp prefix
    float2 s_in;               // segment incoming state
    float  sx[NCH * STRIDE];   // staged samples / y0 (addr = 33*ch + j)
};
#define SMEM_BYTES ((int)sizeof(SmemLayout))

__device__ int    g_flag[NBLK];
__device__ float2 g_state[NBLK];   // zero-state segment totals D_seg

__global__ void init_flags_kernel() {
    int i = blockIdx.x * blockDim.x + threadIdx.x;
    if (i < NBLK) g_flag[i] = 0;
}

#define MATSQ(p00,p01,p10,p11) do {                                  \
    float _t00 = fmaf(p00, p00, p01 * p10);                          \
    float _t01 = p01 * (p00 + p11);                                  \
    float _t10 = p10 * (p00 + p11);                                  \
    float _t11 = fmaf(p11, p11, p01 * p10);                          \
    p00 = _t00; p01 = _t01; p10 = _t10; p11 = _t11; } while (0)

// m <- e * m
#define MATMUL_L(e00,e01,e10,e11, m00,m01,m10,m11) do {              \
    float _r00 = fmaf(e00, m00, e01 * m10);                          \
    float _r01 = fmaf(e00, m01, e01 * m11);                          \
    float _r10 = fmaf(e10, m00, e11 * m10);                          \
    float _r11 = fmaf(e10, m01, e11 * m11);                          \
    m00 = _r00; m01 = _r01; m10 = _r10; m11 = _r11; } while (0)

__global__ __launch_bounds__(THREADS, 4)
void biquad_kernel(const float* __restrict__ x,
                   const float* __restrict__ gb0,
                   const float* __restrict__ gb1,
                   const float* __restrict__ gb2,
                   const float* __restrict__ ga1,
                   const float* __restrict__ ga2,
                   float* __restrict__ out)
{
    extern __shared__ char smem_raw[];
    SmemLayout* S = (SmemLayout*)smem_raw;

    const int bid  = blockIdx.x;
    const int c    = bid >> 2;
    const int seg  = bid & 3;
    const int tid  = threadIdx.x;
    const int lane = tid & 31;
    const int warp = tid >> 5;

    const float A1 = ga1[c], A2 = ga2[c];

    // ---- Q = M^32 : M^2, then 4 squarings ----
    float q00 = fmaf(A1, A1, -A2), q01 = -A1, q10 = A1 * A2, q11 = -A2;  // M^2
    #pragma unroll
    for (int k = 0; k < 4; k++) MATSQ(q00,q01,q10,q11);                  // M^32

    // ---- tables (parallel with load) ----
    if (tid < 32) {                       // mj[tid] = row0 of M^tid
        float r00 = 1.f, r01 = 0.f, r10 = 0.f, r11 = 1.f;
        float e00 = -A1, e01 = 1.f, e10 = -A2, e11 = 0.f;
        #pragma unroll
        for (int k = 0; k < 5; k++) {
            if ((tid >> k) & 1) MATMUL_L(e00,e01,e10,e11, r00,r01,r10,r11);
            MATSQ(e00,e01,e10,e11);
        }
        S->mj[tid] = make_float2(r00, r01);
    } else if (tid < 64) {                // gt[n-1] = Q^n, n = 1..32
        int n = tid - 31;
        float r00 = 1.f, r01 = 0.f, r10 = 0.f, r11 = 1.f;
        float e00 = q00, e01 = q01, e10 = q10, e11 = q11;
        #pragma unroll
        for (int k = 0; k < 6; k++) {
            if ((n >> k) & 1) MATMUL_L(e00,e01,e10,e11, r00,r01,r10,r11);
            MATSQ(e00,e01,e10,e11);
        }
        S->gt[tid - 32] = make_float4(r00, r01, r10, r11);
    } else if (tid < 80) {                // gt2[n-1] = (Q^32)^n, n = 1..16
        int n = tid - 63;
        float e00 = q00, e01 = q01, e10 = q10, e11 = q11;
        MATSQ(e00,e01,e10,e11);           // Q^64? no: (Q)^2 -> base must be Q^32
        // careful: q is already Q = M^32, so e = Q^2 here. Rebuild from Q:
        e00 = q00; e01 = q01; e10 = q10; e11 = q11;   // base Q^32-step = Q
        // (Q^32)^n means 32-chunk steps of 32 warps... base is Q32 = Q^32:
        float b00 = q00, b01 = q01, b10 = q10, b11 = q11;
        #pragma unroll
        for (int k = 0; k < 5; k++) MATSQ(b00,b01,b10,b11);   // (M^32)^32 = Q^32
        float r00 = 1.f, r01 = 0.f, r10 = 0.f, r11 = 1.f;
        #pragma unroll
        for (int k = 0; k < 5; k++) {
            if ((n >> k) & 1) MATMUL_L(b00,b01,b10,b11, r00,r01,r10,r11);
            MATSQ(b00,b01,b10,b11);
        }
        S->gt2[tid - 64] = make_float4(r00, r01, r10, r11);
    }

    // ---- load: float4 global -> padded smem (addr = 33*(i>>3) + 4*(i&7)) ----
    const float4* xc4 = (const float4*)(x + (size_t)c * TLEN + (size_t)seg * SEG);
    for (int i = tid; i < NF4; i += THREADS) {
        float4 v = xc4[i];
        float* p = S->sx + STRIDE * (i >> 3) + ((i & 7) << 2);
        p[0] = v.x; p[1] = v.y; p[2] = v.z; p[3] = v.w;
    }
    __syncthreads();                                        // B1

    // ---- thread 511 (idle in passA): gather predecessors, build s_in ----
    if (tid == THREADS - 1) {
        float sx_ = 0.f, sy_ = 0.f;
        if (seg > 0) {
            // P = Q^375  (375 = 0b101110111)
            float P00 = 1.f, P01 = 0.f, P10 = 0.f, P11 = 1.f;
            float e00 = q00, e01 = q01, e10 = q10, e11 = q11;
            #pragma unroll
            for (int k = 0; k < 9; k++) {
                if ((375 >> k) & 1) MATMUL_L(e00,e01,e10,e11, P00,P01,P10,P11);
                MATSQ(e00,e01,e10,e11);
            }
            const int base = bid - seg;
            for (int j = 0; j < seg; j++) {
                volatile int* fp = g_flag + base + j;
                while (*fp == 0) { }
                __threadfence();
                volatile float* sp = (volatile float*)&g_state[base + j];
                float dx = sp[0], dy = sp[1];
                float nx = fmaf(P00, sx_, fmaf(P01, sy_, dx));
                float ny = fmaf(P10, sx_, fmaf(P11, sy_, dy));
                sx_ = nx; sy_ = ny;
            }
        }
        S->s_in = make_float2(sx_, sy_);
    }

    // ---- passA: zero-state recurrence, y0 written in place ----
    float z1 = 0.f, z2 = 0.f;
    if (tid < NCH) {
        const float B0 = gb0[c], B1v = gb1[c], B2v = gb2[c];
        float* p = S->sx + tid * STRIDE;
        #pragma unroll
        for (int j = 0; j < CHUNK; j++) {
            float xv = p[j];
            float y  = fmaf(B0, xv, z1);
            float w  = fmaf(B1v, xv, z2);
            z1 = fmaf(-A1, y, w);
            z2 = fmaf(-A2, y, B2v * xv);
            p[j] = y;
        }
    }

    // ---- in-warp inclusive affine scan (zero-state, level matrix Q^(2^l)) ----
    float ex = z1, ey = z2;
    float l00 = q00, l01 = q01, l10 = q10, l11 = q11;
    #pragma unroll
    for (int o = 1; o < 32; o <<= 1) {
        float px = __shfl_up_sync(0xffffffffu, ex, o);
        float py = __shfl_up_sync(0xffffffffu, ey, o);
        if (lane >= o) {
            ex = fmaf(l00, px, fmaf(l01, py, ex));
            ey = fmaf(l10, px, fmaf(l11, py, ey));
        }
        MATSQ(l00,l01,l10,l11);          // exits as Q^32
    }
    if (lane == 31) S->warp_agg[warp] = make_float2(ex, ey);
    __syncthreads();                                        // B2 (s_in now valid)

    // ---- cross-warp scan (zero-state) + seeded variant by warp 0 ----
    if (warp == 0) {
        float wx = 0.f, wy = 0.f;
        if (lane < 16) { float2 t = S->warp_agg[lane]; wx = t.x; wy = t.y; }
        #pragma unroll
        for (int o = 1; o < 16; o <<= 1) {
            float px = __shfl_up_sync(0xffffffffu, wx, o);
            float py = __shfl_up_sync(0xffffffffu, wy, o);
            if (lane >= o && lane < 16) {
                wx = fmaf(l00, px, fmaf(l01, py, wx));
                wy = fmaf(l10, px, fmaf(l11, py, wy));
            }
            MATSQ(l00,l01,l10,l11);
        }
        if (lane < 16) {
            S->warp_E[lane] = make_float2(wx, wy);
            float2 si = S->s_in;
            float4 g2 = S->gt2[lane];
            float hx = fmaf(g2.x, si.x, fmaf(g2.y, si.y, wx));
            float hy = fmaf(g2.z, si.x, fmaf(g2.w, si.y, wy));
            S->warp_E2[lane] = make_float2(hx, hy);
        }
    }
    __syncthreads();                                        // B3

    // ---- apply: true state e' = w + Q^(lane+1) * E^_{warp-1}, E^_{-1}=s_in ----
    float2 si = S->s_in;
    float Ehx = si.x, Ehy = si.y;
    float Ezx = 0.f,  Ezy = 0.f;
    if (warp > 0) {
        float2 th = S->warp_E2[warp - 1]; Ehx = th.x; Ehy = th.y;
        float2 tz = S->warp_E [warp - 1]; Ezx = tz.x; Ezy = tz.y;
    }
    float4 g = S->gt[lane];
    float tx = fmaf(g.x, Ehx, fmaf(g.y, Ehy, ex));
    float ty = fmaf(g.z, Ehx, fmaf(g.w, Ehy, ey));

    // ---- publish ZERO-STATE segment total (thread NCH-1) ----
    if (tid == NCH - 1 && seg < NSEG - 1) {
        float zx = fmaf(g.x, Ezx, fmaf(g.y, Ezy, ex));
        float zy = fmaf(g.z, Ezx, fmaf(g.w, Ezy, ey));
        volatile float* dp = (volatile float*)&g_state[bid];
        dp[0] = zx; dp[1] = zy;
        __threadfence();
        *((volatile int*)(g_flag + bid)) = 1;
    }

    // previous chunk's true incoming state
    float pex = __shfl_up_sync(0xffffffffu, tx, 1);
    float pey = __shfl_up_sync(0xffffffffu, ty, 1);
    if (lane == 0) { pex = Ehx; pey = Ehy; }
    if (tid < 384) S->sv_in[tid] = make_float2(pex, pey);
    __syncthreads();                                        // B4

    // ---- store: y = y0 + row0(M^j) . sv_in[chunk], float4 STG ----
    float4* oc4 = (float4*)(out + (size_t)c * TLEN + (size_t)seg * SEG);
    const float4* mjp = (const float4*)S->mj;
    for (int i = tid; i < NF4; i += THREADS) {
        int ch = i >> 3;
        int b  = i & 7;
        float2 s = S->sv_in[ch];
        const float* p = S->sx + STRIDE * ch + (b << 2);
        float4 r01 = mjp[2 * b];
        float4 r23 = mjp[2 * b + 1];
        float4 v;
        v.x = fmaf(r01.x, s.x, fmaf(r01.y, s.y, p[0]));
        v.y = fmaf(r01.z, s.x, fmaf(r01.w, s.y, p[1]));
        v.z = fmaf(r23.x, s.x, fmaf(r23.y, s.y, p[2]));
        v.w = fmaf(r23.z, s.x, fmaf(r23.w, s.y, p[3]));
        oc4[i] = v;
    }
}

extern "C" void kernel_launch(void* const* d_in, const int* in_sizes, int n_in,
                              void* d_out, int out_size)
{
    const float* x  = (const float*)d_in[0];
    const float* b0 = (const float*)d_in[1];
    const float* b1 = (const float*)d_in[2];
    const float* b2 = (const float*)d_in[3];
    const float* a1 = (const float*)d_in[4];
    const float* a2 = (const float*)d_in[5];
    float* out = (float*)d_out;

    cudaFuncSetAttribute(biquad_kernel,
                         cudaFuncAttributeMaxDynamicSharedMemorySize,
                         SMEM_BYTES);

    init_flags_kernel<<<NBLK / THREADS, THREADS>>>();
    biquad_kernel<<<NBLK, THREADS, SMEM_BYTES>>>(x, b0, b1, b2, a1, a2, out);
}